// round 6
// baseline (speedup 1.0000x reference)
#include <cuda_runtime.h>

// Slice_windows: (32,1,1024,1024) f32 -> (32,8) f32
//
// R6: barrier-free streaming. One warp owns a 64x64 region; all levels
// k=2..64 are computed with registers + shuffles only (no smem, no
// __syncthreads in the hot loop), so the 32 LDG.128 per warp stream freely.
// Lane duplication from shuffle-folds is spent computing the p-term on the
// low half and the (1-p)-term on the high half (u = cu + du*S), halving
// MUFU work; residual dup factors are exact powers of two.
// Region sums go to g_64; k=128/256 + all means are done by the
// last-arriving CTA (deterministic fixed-order sums).

#define NBATCH   32
#define NREG     8192         // 32 images * 16 * 16 regions of 64x64
#define NCTAS    1024         // 8 warps/CTA, 1 region per warp
#define NTHREADS 256
#define TINY     1.17549435e-38f

__device__ float g_parts[6 * NCTAS];   // [level][cta]
__device__ float g_64[NREG];           // per-region total sum
__device__ int   g_count = 0;

__device__ __forceinline__ float plog(float u) {
    return u * __log2f(fmaxf(u, TINY));
}

__global__ void __launch_bounds__(NTHREADS, 4)
slice_windows(const float* __restrict__ x, float* __restrict__ out)
{
    __shared__ float s_wp[8][6];
    __shared__ bool  is_last;

    const int tid  = threadIdx.x;
    const int lane = tid & 31;
    const int warp = tid >> 5;
    const int bid  = blockIdx.x;

    const int reg = bid * 8 + warp;        // 0..8191, CTA stays in one image
    const int img = reg >> 8;
    const int ry  = (reg >> 4) & 15;
    const int rx  = reg & 15;

    const int   c16  = lane & 15;          // column group (4 cols)
    const int   rsel = lane >> 4;          // 0: row 2i, 1: row 2i+1
    const float cu   = rsel ? 1.f : 0.f;   // u = cu + du*S  (p or 1-p)
    const float sg   = rsel ? -1.f : 1.f;
    const float du2  = sg * 0.25f;
    const float du4  = sg * (1.f / 16.f);
    const float du8  = sg * (1.f / 64.f);
    const float du16 = sg * (1.f / 256.f);
    const float du32 = sg * (1.f / 1024.f);
    const float du64 = sg * (1.f / 4096.f);

    const float* p0 = x + (size_t)img * (1024 * 1024)
                        + (size_t)(ry * 64 + rsel) * 1024 + rx * 64 + c16 * 4;

    float e2a = 0.f, e2b = 0.f, e4 = 0.f, e8 = 0.f,
          e16 = 0.f, e32 = 0.f, e64 = 0.f;
    float p4 = 0.f, p8r = 0.f, p16r = 0.f, p32r = 0.f, p64r = 0.f;
    float S64 = 0.f;

#pragma unroll
    for (int i = 0; i < 32; ++i) {
        const float4 a = *(const float4*)(p0 + (size_t)i * 2048);
        const float s0 = a.x + a.y;
        const float s1 = a.z + a.w;
        const float v0 = s0 + __shfl_xor_sync(0xffffffffu, s0, 16); // 2x2
        const float v1 = s1 + __shfl_xor_sync(0xffffffffu, s1, 16);
        // k=2 (2 windows per lane-pair; no duplication with u-trick)
        {
            const float u0 = fmaf(v0, du2, cu);
            const float u1 = fmaf(v1, du2, cu);
            e2a = fmaf(u0, __log2f(fmaxf(u0, TINY)), e2a);
            e2b = fmaf(u1, __log2f(fmaxf(u1, TINY)), e2b);
        }
        const float r4 = v0 + v1;                 // 2r x 4c
        if ((i & 1) == 0) { p4 = r4; }
        else {
            const float S4 = p4 + r4;             // 4x4 window
            {
                const float u = fmaf(S4, du4, cu);
                e4 = fmaf(u, __log2f(fmaxf(u, TINY)), e4);
            }
            if ((i & 2) == 0) { p8r = S4; }
            else {
                const float S8r = p8r + S4;       // 8r x 4c
                const float S8  = S8r + __shfl_xor_sync(0xffffffffu, S8r, 1);
                {
                    const float u = fmaf(S8, du8, cu);
                    e8 = fmaf(u, __log2f(fmaxf(u, TINY)), e8);   // dup x2
                }
                if ((i & 4) == 0) { p16r = S8; }
                else {
                    const float S16r = p16r + S8; // 16r x 8c
                    const float S16  = S16r + __shfl_xor_sync(0xffffffffu, S16r, 2);
                    {
                        const float u = fmaf(S16, du16, cu);
                        e16 = fmaf(u, __log2f(fmaxf(u, TINY)), e16); // dup x4
                    }
                    if ((i & 8) == 0) { p32r = S16; }
                    else {
                        const float S32r = p32r + S16;  // 32r x 16c
                        const float S32  = S32r + __shfl_xor_sync(0xffffffffu, S32r, 4);
                        {
                            const float u = fmaf(S32, du32, cu);
                            e32 = fmaf(u, __log2f(fmaxf(u, TINY)), e32); // dup x8
                        }
                        if ((i & 16) == 0) { p64r = S32; }
                        else {
                            const float S64r = p64r + S32;  // 64r x 32c
                            S64 = S64r + __shfl_xor_sync(0xffffffffu, S64r, 8);
                            const float u = fmaf(S64, du64, cu);
                            e64 = fmaf(u, __log2f(fmaxf(u, TINY)), e64); // dup x16
                        }
                    }
                }
            }
        }
    }

    // fold duplication factors (exact powers of 2), then butterfly-reduce
    float e2 = e2a + e2b;
    e8  *= 0.5f;
    e16 *= 0.25f;
    e32 *= 0.125f;
    e64 *= 0.0625f;
#pragma unroll
    for (int o = 16; o > 0; o >>= 1) {
        e2  += __shfl_xor_sync(0xffffffffu, e2,  o);
        e4  += __shfl_xor_sync(0xffffffffu, e4,  o);
        e8  += __shfl_xor_sync(0xffffffffu, e8,  o);
        e16 += __shfl_xor_sync(0xffffffffu, e16, o);
        e32 += __shfl_xor_sync(0xffffffffu, e32, o);
        e64 += __shfl_xor_sync(0xffffffffu, e64, o);
    }
    if (lane == 0) {
        g_64[reg] = S64;
        s_wp[warp][0] = e2;  s_wp[warp][1] = e4;  s_wp[warp][2] = e8;
        s_wp[warp][3] = e16; s_wp[warp][4] = e32; s_wp[warp][5] = e64;
    }
    __syncthreads();
    if (tid < 6) {
        float s = 0.f;
#pragma unroll
        for (int w = 0; w < 8; w++) s += s_wp[w][tid];
        g_parts[tid * NCTAS + bid] = s;
    }
    __threadfence();
    __syncthreads();
    if (tid == 0) {
        const int prev = atomicAdd(&g_count, 1);
        is_last = (prev == NCTAS - 1);
    }
    __syncthreads();

    if (is_last) {
        const int b = tid >> 3;
        const int l = tid & 7;
        if (l < 6) {
            // sum this image's 32 CTA partials (bids [32b, 32b+32))
            const float* gp = g_parts + l * NCTAS + b * 32;
            float s = 0.f;
#pragma unroll
            for (int j = 0; j < 32; j++) s += __ldcg(gp + j);
            const int d = 1024 >> (l + 1);       // windows per side
            out[b * 8 + l] = -s / (float)(d * d);
        } else if (l == 6) {
            // k=128: 8x8 windows of 2x2 regions
            const float* h = g_64 + (b << 8);
            float s = 0.f;
            for (int wy = 0; wy < 8; wy++)
#pragma unroll
                for (int wx = 0; wx < 8; wx++) {
                    const float S = __ldcg(h + (2 * wy) * 16 + 2 * wx)
                                  + __ldcg(h + (2 * wy) * 16 + 2 * wx + 1)
                                  + __ldcg(h + (2 * wy + 1) * 16 + 2 * wx)
                                  + __ldcg(h + (2 * wy + 1) * 16 + 2 * wx + 1);
                    const float p = S * (1.f / 16384.f);
                    s += plog(p) + plog(1.f - p);
                }
            out[b * 8 + 6] = -s / 64.f;
        } else {
            // k=256: 4x4 windows of 4x4 regions
            const float* h = g_64 + (b << 8);
            float s = 0.f;
            for (int wy = 0; wy < 4; wy++)
#pragma unroll
                for (int wx = 0; wx < 4; wx++) {
                    float S = 0.f;
#pragma unroll
                    for (int r = 0; r < 4; r++)
#pragma unroll
                        for (int c = 0; c < 4; c++)
                            S += __ldcg(h + (4 * wy + r) * 16 + 4 * wx + c);
                    const float p = S * (1.f / 65536.f);
                    s += plog(p) + plog(1.f - p);
                }
            out[b * 8 + 7] = -s / 16.f;
        }
        if (tid == 0) g_count = 0;   // reset for graph replay
    }
}

extern "C" void kernel_launch(void* const* d_in, const int* in_sizes, int n_in,
                              void* d_out, int out_size)
{
    (void)in_sizes; (void)n_in; (void)out_size;
    const float* x = (const float*)d_in[0];
    float* out = (float*)d_out;
    slice_windows<<<NCTAS, NTHREADS>>>(x, out);
}

// round 7
// speedup vs baseline: 1.3282x; 1.3282x over previous
#include <cuda_runtime.h>

// Slice_windows: (32,1,1024,1024) f32 -> (32,8) f32
//
// R7 = R1 main kernel (empirically the fastest streaming structure: 26.7us,
// 5.03 TB/s) + fused finalize (saves the 4.5us second launch) + unroll 8.
//  - One CTA per 256x256 tile (512 CTAs, 512 threads, occ 2, no reg cap).
//  - Gmem pass: k=2 sums+entropy in registers, 128x128 sums -> smem.
//  - Smem pyramid k=4..256.
//  - Last-arriving CTA reduces the 512x8 partials in fixed order.

#define NLEVELS 8
#define TILES_PER_IMG 16
#define NBATCH 32
#define NBLOCKS (NBATCH * TILES_PER_IMG)
#define NTHREADS 512

// pyramid: 128^2 + 64^2 + ... + 1 = 21845 floats
#define SMEM_FLOATS 21845
#define SMEM_BYTES (SMEM_FLOATS * 4)

__device__ float g_partials[NBLOCKS * NLEVELS];
__device__ int   g_count = 0;

__device__ __forceinline__ float plogp(float p) {
    // p * log2(p), 0 at p == 0 (matches ref where(p>0,p,1))
    return p * __log2f(fmaxf(p, 1.17549435e-38f));
}
__device__ __forceinline__ float ent(float s, float inv_n) {
    const float p = s * inv_n;
    return plogp(p) + plogp(1.f - p);
}

__global__ void __launch_bounds__(NTHREADS, 2)
slice_windows_fused(const float* __restrict__ x, float* __restrict__ out)
{
    extern __shared__ float sm[];
    __shared__ bool is_last;

    const int tid  = threadIdx.x;
    const int bid  = blockIdx.x;
    const int b    = bid >> 4;
    const int tile = bid & 15;
    const int row0 = (tile >> 2) * 256;
    const int col0 = (tile & 3) * 256;
    const float* __restrict__ img = x + (size_t)b * 1024 * 1024;

    float eacc[NLEVELS];
#pragma unroll
    for (int l = 0; l < NLEVELS; l++) eacc[l] = 0.f;

    // ---- Gmem pass (k=2): read tile, write 128x128 sums to sm[0..16383]
    {
        const float inv_n = 0.25f;
        const int r  = tid >> 6;   // 0..7
        const int c4 = tid & 63;   // 2 outputs per row via float4
#pragma unroll 8
        for (int it = 0; it < 16; ++it) {
            const int orow = it * 8 + r;            // 0..127
            const int grow = row0 + orow * 2;
            const float4 a0 = *((const float4*)(img + (size_t)grow * 1024 + col0) + c4);
            const float4 a1 = *((const float4*)(img + (size_t)(grow + 1) * 1024 + col0) + c4);
            const float s0 = (a0.x + a0.y) + (a1.x + a1.y);
            const float s1 = (a0.z + a0.w) + (a1.z + a1.w);
            eacc[0] -= ent(s0, inv_n) + ent(s1, inv_n);
            sm[orow * 128 + c4 * 2]     = s0;
            sm[orow * 128 + c4 * 2 + 1] = s1;
        }
    }
    __syncthreads();

    // ---- Pyramid in smem: levels l=1..7 (k=4..256), 128x128 -> 1x1
    int in_off = 0, in_dim = 128, out_off = 16384;
#pragma unroll
    for (int l = 1; l < NLEVELS; l++) {
        const int out_dim = in_dim >> 1;
        const int nout = out_dim * out_dim;
        const float inv_n = 1.0f / (float)(1 << (2 * (l + 1)));  // 1/k^2
        for (int i = tid; i < nout; i += NTHREADS) {
            const int oy = i / out_dim;
            const int ox = i - oy * out_dim;
            const float* rp0 = sm + in_off + (2 * oy) * in_dim + 2 * ox;
            const float* rp1 = rp0 + in_dim;
            const float s = (rp0[0] + rp0[1]) + (rp1[0] + rp1[1]);
            eacc[l] -= ent(s, inv_n);
            sm[out_off + i] = s;
        }
        __syncthreads();
        in_off = out_off;
        in_dim = out_dim;
        out_off += nout;
    }
    // level-0 smem region is dead now -> reuse for the block reduction

    // ---- Block-reduce the 8 per-thread entropy accumulators (16 warps)
    const int lane = tid & 31;
    const int warp = tid >> 5;
#pragma unroll
    for (int l = 0; l < NLEVELS; l++) {
        float v = eacc[l];
#pragma unroll
        for (int o = 16; o > 0; o >>= 1)
            v += __shfl_down_sync(0xffffffffu, v, o);
        if (lane == 0) sm[warp * NLEVELS + l] = v;
    }
    __syncthreads();
    if (tid < NLEVELS) {
        float s = 0.f;
#pragma unroll
        for (int w = 0; w < 16; w++) s += sm[w * NLEVELS + tid];
        g_partials[bid * NLEVELS + tid] = s;
    }

    // ---- Fused finalize: last-arriving CTA reduces all partials
    __threadfence();
    if (tid == 0) {
        const int prev = atomicAdd(&g_count, 1);
        is_last = (prev == NBLOCKS - 1);
    }
    __syncthreads();
    if (is_last) {
        if (tid < NBATCH * NLEVELS) {
            const int bb = tid >> 3;
            const int l  = tid & 7;
            float s = 0.f;
#pragma unroll
            for (int t = 0; t < TILES_PER_IMG; t++)
                s += __ldcg(&g_partials[(bb * TILES_PER_IMG + t) * NLEVELS + l]);
            const int d = 1024 >> (l + 1);   // windows per side, k = 2^(l+1)
            out[bb * NLEVELS + l] = s / (float)(d * d);
        }
        if (tid == 0) g_count = 0;           // reset for graph replay
    }
}

extern "C" void kernel_launch(void* const* d_in, const int* in_sizes, int n_in,
                              void* d_out, int out_size)
{
    (void)in_sizes; (void)n_in; (void)out_size;
    const float* x = (const float*)d_in[0];
    float* out = (float*)d_out;

    cudaFuncSetAttribute(slice_windows_fused,
                         cudaFuncAttributeMaxDynamicSharedMemorySize, SMEM_BYTES);
    slice_windows_fused<<<NBLOCKS, NTHREADS, SMEM_BYTES>>>(x, out);
}